// round 4
// baseline (speedup 1.0000x reference)
#include <cuda_runtime.h>
#include <cuda_bf16.h>

#define HID 32
#define CUTOFF_SQ 6.25f
#define THREADS 256
#define TBL 8192        // table intervals over r^2 in [0, 6.25); TBL+1 entries
#define NMAX 4096

__device__ float  g_tbl[TBL + 1];
__device__ float4 g_pos[NMAX];

// Setup: zero out, pack coords to float4 SoA, build e(r^2) table.
// One warp per table entry: lane = hidden unit, warp-shuffle reduce.
__global__ __launch_bounds__(THREADS)
void setup_kernel(const float* __restrict__ xyz,
                  const float* __restrict__ W1,
                  const float* __restrict__ b1,
                  const float* __restrict__ W2,
                  const float* __restrict__ b2,
                  float* __restrict__ out,
                  int n) {
    int t = blockIdx.x * blockDim.x + threadIdx.x;
    if (t == 0) out[0] = 0.0f;

    if (t < n) {
        g_pos[t] = make_float4(xyz[3 * t + 0], xyz[3 * t + 1], xyz[3 * t + 2], 0.0f);
    }

    int warp = t >> 5;
    int lane = t & 31;
    if (warp <= TBL) {
        float r2 = (CUTOFF_SQ / (float)TBL) * (float)warp;
        float r  = sqrtf(r2);
        float v  = W2[lane] * tanhf(fmaf(r, W1[lane], b1[lane]));
        #pragma unroll
        for (int off = 16; off > 0; off >>= 1)
            v += __shfl_xor_sync(0xFFFFFFFFu, v, off);
        if (lane == 0) g_tbl[warp] = v + b2[0];
    }
}

// Block b handles rows b and n-1-b (triangular load balance).
__global__ __launch_bounds__(THREADS)
void pair_energy_kernel(const float* __restrict__ cell_diag,
                        float* __restrict__ out,
                        int n) {
    __shared__ float warp_sums[THREADS / 32];

    const int tid = threadIdx.x;

    const float Lx = cell_diag[0], Ly = cell_diag[1], Lz = cell_diag[2];
    const float iLx = 1.0f / Lx, iLy = 1.0f / Ly, iLz = 1.0f / Lz;
    const float invDr2 = (float)TBL / CUTOFF_SQ;

    float acc = 0.0f;

    #pragma unroll
    for (int half = 0; half < 2; half++) {
        int i = half ? (n - 1 - blockIdx.x) : blockIdx.x;
        if (half && i == (int)blockIdx.x) break;   // odd-n middle row

        const float4 pi = g_pos[i];

        for (int j = i + 1 + tid; j < n; j += THREADS) {
            float4 pj = g_pos[j];
            float dx = pj.x - pi.x;
            float dy = pj.y - pi.y;
            float dz = pj.z - pi.z;

            // minimum image: equivalent to reference offset rule for d in (-L, L)
            dx = fmaf(rintf(dx * iLx), -Lx, dx);
            dy = fmaf(rintf(dy * iLy), -Ly, dy);
            dz = fmaf(rintf(dz * iLz), -Lz, dz);

            float r2 = fmaf(dx, dx, fmaf(dy, dy, dz * dz));

            if (r2 < CUTOFF_SQ && r2 > 0.0f) {
                float t = r2 * invDr2;
                int k = (int)t;
                float f = t - (float)k;
                float e0 = g_tbl[k];
                float e1 = g_tbl[k + 1];
                acc += fmaf(f, e1 - e0, e0);
            }
        }
    }

    #pragma unroll
    for (int off = 16; off > 0; off >>= 1)
        acc += __shfl_down_sync(0xFFFFFFFFu, acc, off);

    int lane = tid & 31;
    int wid = tid >> 5;
    if (lane == 0) warp_sums[wid] = acc;
    __syncthreads();

    if (wid == 0) {
        float v = (lane < THREADS / 32) ? warp_sums[lane] : 0.0f;
        #pragma unroll
        for (int off = 16; off > 0; off >>= 1)
            v += __shfl_down_sync(0xFFFFFFFFu, v, off);
        if (lane == 0) {
            atomicAdd(out, v);
        }
    }
}

extern "C" void kernel_launch(void* const* d_in, const int* in_sizes, int n_in,
                              void* d_out, int out_size) {
    const float* xyz       = (const float*)d_in[0];
    const float* cell_diag = (const float*)d_in[1];
    const float* W1        = (const float*)d_in[2];
    const float* b1        = (const float*)d_in[3];
    const float* W2        = (const float*)d_in[4];
    const float* b2        = (const float*)d_in[5];
    float* out = (float*)d_out;

    int n = in_sizes[0] / 3;

    // setup grid: (TBL+1) warps for the table, plus coverage for n coords
    long setup_threads_tbl = (long)(TBL + 1) * 32;
    long setup_threads = setup_threads_tbl > n ? setup_threads_tbl : n;
    int setup_blocks = (int)((setup_threads + THREADS - 1) / THREADS);
    setup_kernel<<<setup_blocks, THREADS>>>(xyz, W1, b1, W2, b2, out, n);

    int nblocks = (n + 1) / 2;
    pair_energy_kernel<<<nblocks, THREADS>>>(cell_diag, out, n);
}